// round 2
// baseline (speedup 1.0000x reference)
#include <cuda_runtime.h>

#define NMAX 100000
#define DD   128
#define NLYR 3

// Device scratch (no allocations allowed in kernel_launch).
// g_all: [N, 4*128] concatenated embeddings (block0 = raw emb, blocks 1..3 normalized)
// g_ego: [N, 128]   UNNORMALIZED ego propagated between layers
// g_msg: [N, 128]   segment-sum accumulator
__device__ __align__(16) float g_all[(size_t)NMAX * 512];
__device__ __align__(16) float g_ego[(size_t)NMAX * 128];
__device__ __align__(16) float g_msg[(size_t)NMAX * 128];
__device__ __align__(16) float g_wPg[NLYR * 128 * 128];
__device__ __align__(16) float g_wPb[NLYR * 128 * 128];

// ---------------------------------------------------------------------------
// Pack gc_w / bi_w: wP[l][k4*512 + o*4 + j] = W[l][o][4*k4+j] so one LDG.128
// fetches 4 consecutive-k weights for one output dim.
// ---------------------------------------------------------------------------
__global__ void pack_weights(const float* __restrict__ gw,
                             const float* __restrict__ bw) {
    int idx = blockIdx.x * blockDim.x + threadIdx.x;
    if (idx >= NLYR * 128 * 128) return;
    int l = idx >> 14;
    int r = idx & 16383;
    int o = r >> 7;       // output dim (row of W)
    int k = r & 127;      // input dim  (col of W)
    int dst = l * 16384 + (k >> 2) * 512 + o * 4 + (k & 3);
    g_wPg[dst] = gw[idx];
    g_wPb[dst] = bw[idx];
}

// ---------------------------------------------------------------------------
// Copy emb into column block 0 of g_all AND into g_ego; zero g_msg.
// ---------------------------------------------------------------------------
__global__ void init_copy(const float4* __restrict__ emb4, int n) {
    int i = blockIdx.x * blockDim.x + threadIdx.x;
    if (i >= n * 32) return;
    int node = i >> 5, d4 = i & 31;
    float4 v = emb4[i];
    ((float4*)g_all)[(size_t)node * 128 + d4] = v;
    ((float4*)g_ego)[i] = v;
    ((float4*)g_msg)[i] = make_float4(0.f, 0.f, 0.f, 0.f);
}

// ---------------------------------------------------------------------------
// SpMM: msg[row] += w * ego[col].  One warp per edge, float4 atomics (RED.128).
// Gathers from g_ego (unnormalized ego — matches reference semantics).
// ---------------------------------------------------------------------------
__global__ void spmm(const int* __restrict__ ei, const float* __restrict__ ew,
                     int E) {
    int gt = blockIdx.x * blockDim.x + threadIdx.x;
    int e = gt >> 5, lane = gt & 31;
    if (e >= E) return;
    int row = ei[e];
    int col = ei[E + e];
    float w = ew[e];
    float4 v = ((const float4*)g_ego)[(size_t)col * 32 + lane];
    v.x *= w; v.y *= w; v.z *= w; v.w *= w;
    atomicAdd(((float4*)g_msg) + (size_t)row * 32 + lane, v);
}

// ---------------------------------------------------------------------------
// Fused per-layer dense stage:
//   aggr = msg @ gc_w.T + gc_b ;  bi = (ego*msg) @ bi_w.T + bi_b
//   ego' = leaky_relu(aggr + bi, 0.2)      -> g_ego (next layer input)
//   norm = ego' / max(||ego'||, 1e-12)     -> g_all column block (layer+1)
// Also zeroes g_msg rows after consuming them.
// Block = 128 threads (thread == output dim), tile = 16 nodes.
// ---------------------------------------------------------------------------
__global__ __launch_bounds__(128) void fused_layer(
        const float* __restrict__ gcb, const float* __restrict__ bib,
        int n, int layer) {
    __shared__ __align__(16) float msgS[16 * 128];
    __shared__ __align__(16) float pS[16 * 128];
    __shared__ float invS[16];

    int tid  = threadIdx.x;
    int nb   = blockIdx.x * 16;
    int loff = layer * 128;

    float4* msgS4 = (float4*)msgS;
    float4* pS4   = (float4*)pS;

    // Load msg tile and ego*msg tile; zero msg in gmem behind us.
    for (int i = tid; i < 16 * 32; i += 128) {
        int ln = i >> 5, d4 = i & 31;
        int g = nb + ln;
        float4 m = make_float4(0.f, 0.f, 0.f, 0.f);
        float4 p = m;
        if (g < n) {
            m = ((float4*)g_msg)[(size_t)g * 32 + d4];
            float4 e = ((const float4*)g_ego)[(size_t)g * 32 + d4];
            p.x = m.x * e.x; p.y = m.y * e.y; p.z = m.z * e.z; p.w = m.w * e.w;
            ((float4*)g_msg)[(size_t)g * 32 + d4] = make_float4(0.f, 0.f, 0.f, 0.f);
        }
        msgS4[i] = m;
        pS4[i]   = p;
    }
    __syncthreads();

    const int od = tid;
    const float* wg = g_wPg + layer * 16384;
    const float* wb = g_wPb + layer * 16384;

    float accg[16], accb[16];
#pragma unroll
    for (int i = 0; i < 16; ++i) { accg[i] = 0.f; accb[i] = 0.f; }

    for (int k4 = 0; k4 < 32; ++k4) {
        float4 wg4 = *(const float4*)(wg + k4 * 512 + od * 4);
        float4 wb4 = *(const float4*)(wb + k4 * 512 + od * 4);
#pragma unroll
        for (int nn = 0; nn < 16; ++nn) {
            float4 m = msgS4[nn * 32 + k4];   // broadcast LDS.128
            float4 p = pS4[nn * 32 + k4];
            accg[nn] += wg4.x * m.x;
            accg[nn] += wg4.y * m.y;
            accg[nn] += wg4.z * m.z;
            accg[nn] += wg4.w * m.w;
            accb[nn] += wb4.x * p.x;
            accb[nn] += wb4.y * p.y;
            accb[nn] += wb4.z * p.z;
            accb[nn] += wb4.w * p.w;
        }
    }

    float bsum = gcb[loff + od] + bib[loff + od];
    float v[16];
#pragma unroll
    for (int nn = 0; nn < 16; ++nn) {
        float x = accg[nn] + accb[nn] + bsum;
        v[nn] = (x > 0.f) ? x : 0.2f * x;      // leaky_relu(0.2)
    }

    // L2 norm per node: reuse pS as [node][od] squares.
    __syncthreads();
#pragma unroll
    for (int nn = 0; nn < 16; ++nn) pS[nn * 128 + od] = v[nn] * v[nn];
    __syncthreads();
    {
        int nn = tid >> 3, seg = tid & 7;
        const float* rowp = pS + nn * 128 + seg * 16;
        float s = 0.f;
#pragma unroll
        for (int j = 0; j < 16; ++j) s += rowp[j];
        s += __shfl_xor_sync(0xffffffffu, s, 1);
        s += __shfl_xor_sync(0xffffffffu, s, 2);
        s += __shfl_xor_sync(0xffffffffu, s, 4);
        if (seg == 0) invS[nn] = 1.0f / fmaxf(sqrtf(s), 1e-12f);
    }
    __syncthreads();

#pragma unroll
    for (int nn = 0; nn < 16; ++nn) {
        int g = nb + nn;
        if (g < n) {
            g_ego[(size_t)g * 128 + od] = v[nn];                       // unnormalized -> next layer
            g_all[(size_t)g * 512 + loff + 128 + od] = v[nn] * invS[nn]; // normalized -> concat
        }
    }
}

// ---------------------------------------------------------------------------
// Scoring: out[q] = dot(all[src[q]], all[dst[q]]) over 512 dims.
// One warp per query.
// ---------------------------------------------------------------------------
__global__ void score(const int* __restrict__ eli, int Q,
                      float* __restrict__ out) {
    int gt = blockIdx.x * blockDim.x + threadIdx.x;
    int q = gt >> 5, lane = gt & 31;
    if (q >= Q) return;
    int s = eli[q];
    int d = eli[Q + q];
    const float4* a = (const float4*)(g_all + (size_t)s * 512);
    const float4* b = (const float4*)(g_all + (size_t)d * 512);
    float acc = 0.f;
#pragma unroll
    for (int j = 0; j < 4; ++j) {
        float4 x = a[lane + 32 * j];
        float4 y = b[lane + 32 * j];
        acc += x.x * y.x + x.y * y.y + x.z * y.z + x.w * y.w;
    }
#pragma unroll
    for (int off = 16; off; off >>= 1)
        acc += __shfl_xor_sync(0xffffffffu, acc, off);
    if (lane == 0) out[q] = acc;
}

// ---------------------------------------------------------------------------
extern "C" void kernel_launch(void* const* d_in, const int* in_sizes, int n_in,
                              void* d_out, int out_size) {
    const int*   ei  = (const int*)d_in[0];    // edge_index        [2, E]
    const int*   eli = (const int*)d_in[1];    // edge_label_index  [2, Q]
    const float* ew  = (const float*)d_in[2];  // edge_weight       [E]
    const float* emb = (const float*)d_in[3];  // emb               [N, 128]
    const float* gcw = (const float*)d_in[4];  // gc_w              [3,128,128]
    const float* gcb = (const float*)d_in[5];  // gc_b              [3,128]
    const float* biw = (const float*)d_in[6];  // bi_w              [3,128,128]
    const float* bib = (const float*)d_in[7];  // bi_b              [3,128]

    int E = in_sizes[0] / 2;
    int Q = in_sizes[1] / 2;
    int n = in_sizes[3] / 128;
    float* out = (float*)d_out;

    pack_weights<<<(NLYR * 16384 + 255) / 256, 256>>>(gcw, biw);
    init_copy<<<(n * 32 + 255) / 256, 256>>>((const float4*)emb, n);

    for (int l = 0; l < NLYR; ++l) {
        spmm<<<(int)(((size_t)E * 32 + 255) / 256), 256>>>(ei, ew, E);
        fused_layer<<<(n + 15) / 16, 128>>>(gcb, bib, n, l);
    }

    score<<<(int)(((size_t)Q * 32 + 255) / 256), 256>>>(eli, Q, out);
}

// round 3
// speedup vs baseline: 1.3566x; 1.3566x over previous
#include <cuda_runtime.h>

#define NMAX 100000
#define NLYR 3

// Device scratch.
// g_all : [N, 512]  concatenated embeddings (block0 raw emb, blocks 1..3 normalized)
// g_ego : [N, 128]  UNNORMALIZED ego propagated between layers
// g_msg : [N, 128]  segment-sum accumulator (kept zero between graph replays)
// g_wPack: [l][k=0..255][od] stacked weights: k<128 -> gc_w[l][od][k], else bi_w[l][od][k-128]
__device__ __align__(16) float g_all[(size_t)NMAX * 512];
__device__ __align__(16) float g_ego[(size_t)NMAX * 128];
__device__ __align__(16) float g_msg[(size_t)NMAX * 128];
__device__ __align__(16) float g_wPack[NLYR * 256 * 128];

// packed f32x2 fma: d = a*b + d (2 independent fp32 lanes per instruction)
__device__ __forceinline__ void fma2(unsigned long long& d,
                                     unsigned long long a,
                                     unsigned long long b) {
    asm("fma.rn.f32x2 %0, %1, %2, %0;" : "+l"(d) : "l"(a), "l"(b));
}

// ---------------------------------------------------------------------------
__global__ void pack_weights(const float* __restrict__ gw,
                             const float* __restrict__ bw) {
    int idx = blockIdx.x * blockDim.x + threadIdx.x;
    if (idx >= NLYR * 256 * 128) return;
    int l  = idx >> 15;
    int r  = idx & 32767;
    int k  = r >> 7;
    int od = r & 127;
    float v = (k < 128) ? gw[l * 16384 + od * 128 + k]
                        : bw[l * 16384 + od * 128 + (k - 128)];
    g_wPack[idx] = v;
}

// ---------------------------------------------------------------------------
__global__ void init_copy(const float4* __restrict__ emb4, int n) {
    int i = blockIdx.x * blockDim.x + threadIdx.x;
    if (i >= n * 32) return;
    int node = i >> 5, d4 = i & 31;
    float4 v = emb4[i];
    ((float4*)g_all)[(size_t)node * 128 + d4] = v;
    ((float4*)g_ego)[i] = v;
    ((float4*)g_msg)[i] = make_float4(0.f, 0.f, 0.f, 0.f);
}

// ---------------------------------------------------------------------------
// SpMM: msg[row] += w * ego[col]. One warp per edge, float4 atomics (RED.128).
// ---------------------------------------------------------------------------
__global__ void spmm(const int* __restrict__ ei, const float* __restrict__ ew,
                     int E) {
    int gt = blockIdx.x * blockDim.x + threadIdx.x;
    int e = gt >> 5, lane = gt & 31;
    if (e >= E) return;
    int row = ei[e];
    int col = ei[E + e];
    float w = ew[e];
    float4 v = ((const float4*)g_ego)[(size_t)col * 32 + lane];
    v.x *= w; v.y *= w; v.z *= w; v.w *= w;
    atomicAdd(((float4*)g_msg) + (size_t)row * 32 + lane, v);
}

// ---------------------------------------------------------------------------
// Fused layer as register-tiled GEMM with packed f32x2 FMA.
//   C[32 nodes][128 od] = A[32][256] * B[256][128]   (A = [msg | ego*msg])
//   ego' = leaky_relu(C + bias, 0.2) -> g_ego ; normalized -> g_all block l+1
//   zeroes g_msg rows afterwards.
// Block 256 thr = 8 warps; warp w owns nodes 4w..4w+3; lane owns ods 4*lane..
// A stored DUPLICATED in smem ((a,a) pairs) so LDS yields packed multiplicands.
// ---------------------------------------------------------------------------
__global__ __launch_bounds__(256) void fused_layer(
        const float* __restrict__ gcb, const float* __restrict__ bib,
        int n, int layer) {
    __shared__ __align__(16) float As2[64 * 64];    // [kc][2*node]  16KB
    __shared__ __align__(16) float Bs[64 * 128];    // [kc][od]      32KB

    const int tid  = threadIdx.x;
    const int tn   = tid >> 5;      // warp id -> node group
    const int to   = tid & 31;      // lane    -> od group
    const int nb   = blockIdx.x * 32;
    const int loff = layer * 128;
    const float* wP = g_wPack + layer * 32768;

    unsigned long long acc[4][2];
#pragma unroll
    for (int i = 0; i < 4; ++i) { acc[i][0] = 0ull; acc[i][1] = 0ull; }

    for (int c = 0; c < 4; ++c) {
        __syncthreads();
        // --- fill B chunk: wPack[c*64 .. c*64+63][0..127], coalesced float4 ---
        {
            const float4* src = (const float4*)(wP + c * 64 * 128);
            float4* dst = (float4*)Bs;
#pragma unroll
            for (int i = 0; i < 8; ++i) dst[tid + 256 * i] = src[tid + 256 * i];
        }
        // --- fill A chunk (duplicated): 512 float4 reads ---
        {
#pragma unroll
            for (int i = 0; i < 2; ++i) {
                int idx  = tid + 256 * i;      // 0..511
                int node = idx & 31;           // = lane -> conflict-free STS
                int k4   = idx >> 5;           // 0..15
                int g    = nb + node;
                float4 m = make_float4(0.f, 0.f, 0.f, 0.f);
                int kk = c * 64 + k4 * 4;
                if (g < n) {
                    if (kk < 128) {
                        m = *(const float4*)(g_msg + (size_t)g * 128 + kk);
                    } else {
                        m = *(const float4*)(g_msg + (size_t)g * 128 + kk - 128);
                        float4 e = *(const float4*)(g_ego + (size_t)g * 128 + kk - 128);
                        m.x *= e.x; m.y *= e.y; m.z *= e.z; m.w *= e.w;
                    }
                }
                float* base = As2 + (k4 * 4) * 64 + 2 * node;
                *(float2*)(base)       = make_float2(m.x, m.x);
                *(float2*)(base + 64)  = make_float2(m.y, m.y);
                *(float2*)(base + 128) = make_float2(m.z, m.z);
                *(float2*)(base + 192) = make_float2(m.w, m.w);
            }
        }
        __syncthreads();
        // --- compute 64 k-steps: 3 LDS.128 + 8 FFMA2 per k ---
        const ulonglong2* Bu = (const ulonglong2*)Bs;    // 32 ull2 per k row
        const ulonglong2* Au = (const ulonglong2*)As2;   // 16 ull2 per k row
#pragma unroll 8
        for (int k = 0; k < 64; ++k) {
            ulonglong2 b   = Bu[k * 32 + to];            // ods 4to..4to+3
            ulonglong2 a01 = Au[k * 16 + 2 * tn];        // (n0,n0),(n1,n1)
            ulonglong2 a23 = Au[k * 16 + 2 * tn + 1];    // (n2,n2),(n3,n3)
            fma2(acc[0][0], a01.x, b.x); fma2(acc[0][1], a01.x, b.y);
            fma2(acc[1][0], a01.y, b.x); fma2(acc[1][1], a01.y, b.y);
            fma2(acc[2][0], a23.x, b.x); fma2(acc[2][1], a23.x, b.y);
            fma2(acc[3][0], a23.y, b.x); fma2(acc[3][1], a23.y, b.y);
        }
    }

    // --- epilogue: bias, leaky_relu, per-node L2 norm (warp-local), stores ---
    float4 bias;
    {
        float4 bg = *(const float4*)(gcb + loff + 4 * to);
        float4 bb = *(const float4*)(bib + loff + 4 * to);
        bias = make_float4(bg.x + bb.x, bg.y + bb.y, bg.z + bb.z, bg.w + bb.w);
    }

    float4 v[4];
    float  s[4];
#pragma unroll
    for (int nn = 0; nn < 4; ++nn) {
        float x0 = __uint_as_float((unsigned)(acc[nn][0] & 0xffffffffu)) + bias.x;
        float x1 = __uint_as_float((unsigned)(acc[nn][0] >> 32))         + bias.y;
        float x2 = __uint_as_float((unsigned)(acc[nn][1] & 0xffffffffu)) + bias.z;
        float x3 = __uint_as_float((unsigned)(acc[nn][1] >> 32))         + bias.w;
        x0 = (x0 > 0.f) ? x0 : 0.2f * x0;
        x1 = (x1 > 0.f) ? x1 : 0.2f * x1;
        x2 = (x2 > 0.f) ? x2 : 0.2f * x2;
        x3 = (x3 > 0.f) ? x3 : 0.2f * x3;
        v[nn] = make_float4(x0, x1, x2, x3);
        s[nn] = x0 * x0 + x1 * x1 + x2 * x2 + x3 * x3;
    }
#pragma unroll
    for (int off = 16; off; off >>= 1) {
        s[0] += __shfl_xor_sync(0xffffffffu, s[0], off);
        s[1] += __shfl_xor_sync(0xffffffffu, s[1], off);
        s[2] += __shfl_xor_sync(0xffffffffu, s[2], off);
        s[3] += __shfl_xor_sync(0xffffffffu, s[3], off);
    }
    const float4 z4 = make_float4(0.f, 0.f, 0.f, 0.f);
#pragma unroll
    for (int nn = 0; nn < 4; ++nn) {
        int g = nb + 4 * tn + nn;
        if (g < n) {
            float inv = 1.0f / fmaxf(sqrtf(s[nn]), 1e-12f);
            float4 w = v[nn];
            *(float4*)(g_ego + (size_t)g * 128 + 4 * to) = w;
            *(float4*)(g_all + (size_t)g * 512 + loff + 128 + 4 * to) =
                make_float4(w.x * inv, w.y * inv, w.z * inv, w.w * inv);
            *(float4*)(g_msg + (size_t)g * 128 + 4 * to) = z4;  // ready for next spmm
        }
    }
}

// ---------------------------------------------------------------------------
// Scoring: out[q] = dot(all[src[q]], all[dst[q]]) over 512 dims. Warp/query.
// ---------------------------------------------------------------------------
__global__ void score(const int* __restrict__ eli, int Q,
                      float* __restrict__ out) {
    int gt = blockIdx.x * blockDim.x + threadIdx.x;
    int q = gt >> 5, lane = gt & 31;
    if (q >= Q) return;
    int s = eli[q];
    int d = eli[Q + q];
    const float4* a = (const float4*)(g_all + (size_t)s * 512);
    const float4* b = (const float4*)(g_all + (size_t)d * 512);
    float acc = 0.f;
#pragma unroll
    for (int j = 0; j < 4; ++j) {
        float4 x = a[lane + 32 * j];
        float4 y = b[lane + 32 * j];
        acc += x.x * y.x + x.y * y.y + x.z * y.z + x.w * y.w;
    }
#pragma unroll
    for (int off = 16; off; off >>= 1)
        acc += __shfl_xor_sync(0xffffffffu, acc, off);
    if (lane == 0) out[q] = acc;
}

// ---------------------------------------------------------------------------
extern "C" void kernel_launch(void* const* d_in, const int* in_sizes, int n_in,
                              void* d_out, int out_size) {
    const int*   ei  = (const int*)d_in[0];    // edge_index        [2, E]
    const int*   eli = (const int*)d_in[1];    // edge_label_index  [2, Q]
    const float* ew  = (const float*)d_in[2];  // edge_weight       [E]
    const float* emb = (const float*)d_in[3];  // emb               [N, 128]
    const float* gcw = (const float*)d_in[4];  // gc_w              [3,128,128]
    const float* gcb = (const float*)d_in[5];  // gc_b              [3,128]
    const float* biw = (const float*)d_in[6];  // bi_w              [3,128,128]
    const float* bib = (const float*)d_in[7];  // bi_b              [3,128]

    int E = in_sizes[0] / 2;
    int Q = in_sizes[1] / 2;
    int n = in_sizes[3] / 128;
    float* out = (float*)d_out;

    pack_weights<<<(NLYR * 256 * 128 + 255) / 256, 256>>>(gcw, biw);
    init_copy<<<(n * 32 + 255) / 256, 256>>>((const float4*)emb, n);

    for (int l = 0; l < NLYR; ++l) {
        spmm<<<(int)(((size_t)E * 32 + 255) / 256), 256>>>(ei, ew, E);
        fused_layer<<<(n + 31) / 32, 256>>>(gcb, bib, n, l);
    }

    score<<<(int)(((size_t)Q * 32 + 255) / 256), 256>>>(eli, Q, out);
}